// round 16
// baseline (speedup 1.0000x reference)
#include <cuda_runtime.h>
#include <cuda_fp16.h>
#include <math.h>
#include <stdint.h>

// ---------------- problem constants ----------------
#define D_MODEL 512
#define SEQ     1024
#define BATCH   8
#define NHEADS  8
#define UDIM    64
#define FF      2048
#define TOK     (BATCH*SEQ)          // 8192
#define LN_EPS  1e-3f

// ---------------- scratch (static device, allocation-guard safe) -------------
__device__ __half g_x16[TOK*D_MODEL];
__device__ __half g_vw16[NHEADS*D_MODEL*D_MODEL];    // vw cvt, [h][d][e]
__device__ __half g_WqkT[2*D_MODEL*D_MODEL];         // rows 0-511: WqT*scale, 512-1023: WkT
__device__ __half g_lwT[D_MODEL*NHEADS*D_MODEL];     // [f][h*512+e]
__device__ __half g_WfT[NHEADS*D_MODEL*D_MODEL];     // [(h*512+f)][d]  (fused vw@lw)
__device__ __half g_w1T[FF*D_MODEL];                 // [2048][512]
__device__ __half g_w2T[D_MODEL*FF];                 // [512][2048]
__device__ __half g_QK [TOK*2*D_MODEL];              // [t][q:0-511 | k:512-1023]
__device__ __half g_VL [TOK*NHEADS*D_MODEL];         // [t][(h*512+f)]
__device__ __half g_VLt[(size_t)BATCH*D_MODEL*NHEADS*SEQ];  // [(b*512+f)][h*1024+t']
__device__ __half g_S16[(size_t)TOK*NHEADS*SEQ];     // [b*1024+t][h*1024+t'] fp16
__device__ float  g_Mha[TOK*D_MODEL];
__device__ float  g_H  [TOK*D_MODEL];
__device__ __half g_H16[TOK*D_MODEL];
__device__ __half g_F1 [TOK*FF];
__device__ float  g_F2 [TOK*D_MODEL];

// ---------------- cp.async helpers ----------------
__device__ __forceinline__ void cp_async16(unsigned int dst, const void* src) {
    asm volatile("cp.async.cg.shared.global [%0], [%1], 16;\n" :: "r"(dst), "l"(src));
}
__device__ __forceinline__ void cp_commit() {
    asm volatile("cp.async.commit_group;\n");
}
template<int N>
__device__ __forceinline__ void cp_wait() {
    asm volatile("cp.async.wait_group %0;\n" :: "n"(N));
}

// ---------------- elementwise fp32 -> fp16 ----------------
__global__ void cvt16(const float* __restrict__ in, __half* __restrict__ out, int n) {
    int i = blockIdx.x * blockDim.x + threadIdx.x;
    if (i < n) out[i] = __float2half(in[i]);
}

// ---------------- tiled transpose + cvt (+scale): [z][R][C] -> [z][C][R] fp16 --
__global__ void transpose_cvt(const float* __restrict__ in, __half* __restrict__ out,
                              int R, int C, long long inZ, long long outZ, float scl) {
    in  += (long long)blockIdx.z * inZ;
    out += (long long)blockIdx.z * outZ;
    __shared__ float s[32][33];
    int c0 = blockIdx.x * 32, r0 = blockIdx.y * 32;
    int tx = threadIdx.x, ty = threadIdx.y;
#pragma unroll
    for (int j = 0; j < 4; j++)
        s[ty + 8 * j][tx] = in[(long long)(r0 + ty + 8 * j) * C + c0 + tx];
    __syncthreads();
#pragma unroll
    for (int j = 0; j < 4; j++)
        out[(long long)(c0 + ty + 8 * j) * R + r0 + tx] =
            __float2half(s[tx][ty + 8 * j] * scl);
}

// ---------------- VL transpose: VL[t][(h*512+f)] -> VLt[(b*512+f)][h*1024+t'] --
__global__ void transpose_vl(const __half* __restrict__ VL, __half* __restrict__ VLt) {
    int z = blockIdx.z, b = z >> 3, h = z & 7;
    int c0 = blockIdx.x * 32;   // f
    int r0 = blockIdx.y * 32;   // t'
    __shared__ __half s[32][40];
    int tx = threadIdx.x, ty = threadIdx.y;
#pragma unroll
    for (int j = 0; j < 4; j++)
        s[ty + 8 * j][tx] = VL[(size_t)(b * 1024 + r0 + ty + 8 * j) * 4096 + h * 512 + c0 + tx];
    __syncthreads();
#pragma unroll
    for (int j = 0; j < 4; j++)
        VLt[(size_t)(b * 512 + c0 + ty + 8 * j) * 8192 + h * 1024 + r0 + tx] = s[tx][ty + 8 * j];
}

// ---------------- fp16 NT tensor-core GEMM  128x128xK, 256 thr ----------------
// 8 warps (2x4), 64x32 warp tile.  mma.sync.m16n8k16 fp32-accum.
// k64 iterations = two consecutive k32 sub-blocks; each sub-block uses the
// verified layout: rows of 32 halves (64B), 16B-group swizzle j^((row>>1)&3),
// k-remap (thread t4 carries global k {4t4..4t4+3}).  All STS/LDS
// conflict-free as before (addressing within sub-block unchanged).
// 3-stage cp.async pipeline, 96KB dynamic smem, 2 CTAs/SM, ONE barrier per
// k64 iteration.  K%64==0, M,N%128==0.
#define STAGES 3
#define STG_BYTES 32768u            // per stage: A 16KB + B 16KB (2 sub-blocks each)
#define SMEMSZ (STAGES * 32768)

__global__ void __launch_bounds__(256, 2) gemm16(
    const __half* __restrict__ A, const __half* __restrict__ B,
    float* __restrict__ C32, __half* __restrict__ C16,
    int K, int lda, int ldb, int ldc,
    long long aOut, long long aIn, long long bOut, long long bIn,
    long long cOut, long long cIn, int HB,
    const float* __restrict__ bias, int relu)
{
    extern __shared__ char smem_raw[];
    int z  = blockIdx.z;
    int zo = z / HB, zi = z % HB;
    A += zo * aOut + (long long)zi * aIn;
    B += zo * bOut + (long long)zi * bIn;
    long long coff = zo * cOut + (long long)zi * cIn;

    const int tid  = threadIdx.x;
    const int lane = tid & 31;
    const int wid  = tid >> 5;
    const int wm   = wid >> 2;
    const int wn   = wid & 3;
    const int g    = lane >> 2;
    const int t4   = lane & 3;

    const int bm = blockIdx.y * 128;
    const int bn = blockIdx.x * 128;
    const int KT = K >> 6;              // k64 iterations

    const bool isA = (tid < 128);
    const int  lrow = tid & 127;
    const int  lsw  = (lrow >> 1) & 3;
    const __half* Lg = isA ? (A + (long long)(bm + lrow) * lda)
                           : (B + (long long)(bn + lrow) * ldb);

    unsigned int sb;
    asm("{ .reg .u64 t; cvta.to.shared.u64 t, %1; cvt.u32.u64 %0, t; }"
        : "=r"(sb) : "l"(smem_raw));
    unsigned int sBase = sb + (isA ? 0u : 16384u);

    auto issue = [&](int kt, int s) {
        unsigned int st = sBase + (unsigned int)s * STG_BYTES;
        const __half* src = Lg + (long long)kt * 64;
#pragma unroll
        for (int sub = 0; sub < 2; sub++)
#pragma unroll
            for (int j = 0; j < 4; j++)
                cp_async16(st + (unsigned int)sub * 8192u
                              + (unsigned int)(lrow * 4 + (j ^ lsw)) * 16,
                           src + sub * 32 + j * 8);
    };

    float acc[4][4][4];
#pragma unroll
    for (int mi = 0; mi < 4; mi++)
#pragma unroll
        for (int ni = 0; ni < 4; ni++)
#pragma unroll
            for (int r = 0; r < 4; r++) acc[mi][ni][r] = 0.f;

#pragma unroll
    for (int s = 0; s < STAGES - 1; s++) {
        if (s < KT) issue(s, s);
        cp_commit();
    }

    for (int kt = 0; kt < KT; kt++) {
        cp_wait<STAGES - 2>();
        __syncthreads();
        if (kt + STAGES - 1 < KT) issue(kt + STAGES - 1, (kt + STAGES - 1) % STAGES);
        cp_commit();

        const int st = kt % STAGES;
#pragma unroll
        for (int kk = 0; kk < 4; kk++) {
            const int sub = kk >> 1;
            const uint2* As2 = (const uint2*)(smem_raw + st * STG_BYTES + sub * 8192);
            const uint2* Bs2 = (const uint2*)(smem_raw + st * STG_BYTES + 16384 + sub * 8192);
            const int jb = (kk & 1) * 2 + (t4 >> 1);
            uint2 afr[4][2];
#pragma unroll
            for (int mi = 0; mi < 4; mi++) {
                const int r0 = wm * 64 + mi * 16 + g;
                const int r1 = r0 + 8;
                afr[mi][0] = As2[r0 * 8 + ((jb ^ ((r0 >> 1) & 3)) << 1) + (t4 & 1)];
                afr[mi][1] = As2[r1 * 8 + ((jb ^ ((r1 >> 1) & 3)) << 1) + (t4 & 1)];
            }
#pragma unroll
            for (int ni = 0; ni < 4; ni++) {
                const int n0 = wn * 32 + ni * 8 + g;
                const uint2 bfr = Bs2[n0 * 8 + ((jb ^ ((n0 >> 1) & 3)) << 1) + (t4 & 1)];
#pragma unroll
                for (int mi = 0; mi < 4; mi++) {
                    asm volatile(
                        "mma.sync.aligned.m16n8k16.row.col.f32.f16.f16.f32 "
                        "{%0,%1,%2,%3},{%4,%5,%6,%7},{%8,%9},{%0,%1,%2,%3};\n"
                        : "+f"(acc[mi][ni][0]), "+f"(acc[mi][ni][1]),
                          "+f"(acc[mi][ni][2]), "+f"(acc[mi][ni][3])
                        : "r"(afr[mi][0].x), "r"(afr[mi][1].x),
                          "r"(afr[mi][0].y), "r"(afr[mi][1].y),
                          "r"(bfr.x), "r"(bfr.y));
                }
            }
        }
        // single barrier per k64 (next iteration's top barrier orders reuse)
    }

    // ---- epilogue ----
#pragma unroll
    for (int mi = 0; mi < 4; mi++) {
        const int row0 = bm + wm * 64 + mi * 16 + g;
#pragma unroll
        for (int ni = 0; ni < 4; ni++) {
            const int col = bn + wn * 32 + ni * 8 + t4 * 2;
            float v0 = acc[mi][ni][0], v1 = acc[mi][ni][1];
            float v2 = acc[mi][ni][2], v3 = acc[mi][ni][3];
            if (bias) {
                float b0 = bias[col], b1 = bias[col + 1];
                v0 += b0; v1 += b1; v2 += b0; v3 += b1;
            }
            if (relu) {
                v0 = fmaxf(v0, 0.f); v1 = fmaxf(v1, 0.f);
                v2 = fmaxf(v2, 0.f); v3 = fmaxf(v3, 0.f);
            }
            long long o0 = coff + (long long)row0 * ldc + col;
            long long o1 = coff + (long long)(row0 + 8) * ldc + col;
            if (C32) {
                *(float2*)(C32 + o0) = make_float2(v0, v1);
                *(float2*)(C32 + o1) = make_float2(v2, v3);
            }
            if (C16) {
                *(__half2*)(C16 + o0) = __floats2half2_rn(v0, v1);
                *(__half2*)(C16 + o1) = __floats2half2_rn(v2, v3);
            }
        }
    }
}

// ---------------- in-place fp16 softmax over 1024 cols (fp32 math) -----------
__global__ void softmax_h(__half* __restrict__ P) {
    long long row = blockIdx.x;
    __half2* p = (__half2*)(P + row * 1024);
    int t = threadIdx.x;
    __half2 h0 = p[2 * t], h1 = p[2 * t + 1];
    float2 f0 = __half22float2(h0), f1 = __half22float2(h1);
    float v0 = f0.x, v1 = f0.y, v2 = f1.x, v3 = f1.y;

    __shared__ float red[256];
    float m = fmaxf(fmaxf(v0, v1), fmaxf(v2, v3));
    red[t] = m;
    __syncthreads();
#pragma unroll
    for (int s = 128; s > 0; s >>= 1) {
        if (t < s) red[t] = fmaxf(red[t], red[t + s]);
        __syncthreads();
    }
    m = red[0];
    __syncthreads();

    v0 = __expf(v0 - m); v1 = __expf(v1 - m);
    v2 = __expf(v2 - m); v3 = __expf(v3 - m);
    red[t] = v0 + v1 + v2 + v3;
    __syncthreads();
#pragma unroll
    for (int s = 128; s > 0; s >>= 1) {
        if (t < s) red[t] += red[t + s];
        __syncthreads();
    }
    float inv = 1.f / red[0];
    p[2 * t]     = __floats2half2_rn(v0 * inv, v1 * inv);
    p[2 * t + 1] = __floats2half2_rn(v2 * inv, v3 * inv);
}

// ---------------- out = LayerNorm(a + b); optional fp16 copy ----------------
__global__ void add_ln(const float* __restrict__ a, const float* __restrict__ b,
                       const float* __restrict__ gamma, const float* __restrict__ beta,
                       float* __restrict__ out, __half* __restrict__ out16) {
    long long row = blockIdx.x;
    int t = threadIdx.x;
    const float4 va = ((const float4*)(a + row * 512))[t];
    const float4 vb = ((const float4*)(b + row * 512))[t];
    float x0 = va.x + vb.x, x1 = va.y + vb.y, x2 = va.z + vb.z, x3 = va.w + vb.w;

    __shared__ float red[128];
    red[t] = x0 + x1 + x2 + x3;
    __syncthreads();
#pragma unroll
    for (int s = 64; s > 0; s >>= 1) {
        if (t < s) red[t] += red[t + s];
        __syncthreads();
    }
    float mean = red[0] * (1.f / 512.f);
    __syncthreads();

    float d0 = x0 - mean, d1 = x1 - mean, d2 = x2 - mean, d3 = x3 - mean;
    red[t] = d0 * d0 + d1 * d1 + d2 * d2 + d3 * d3;
    __syncthreads();
#pragma unroll
    for (int s = 64; s > 0; s >>= 1) {
        if (t < s) red[t] += red[t + s];
        __syncthreads();
    }
    float var = red[0] * (1.f / 512.f);
    float inv = rsqrtf(var + LN_EPS);

    const float4 gm = ((const float4*)gamma)[t];
    const float4 be = ((const float4*)beta)[t];
    float4 o;
    o.x = gm.x * (d0 * inv) + be.x;
    o.y = gm.y * (d1 * inv) + be.y;
    o.z = gm.z * (d2 * inv) + be.z;
    o.w = gm.w * (d3 * inv) + be.w;
    ((float4*)(out + row * 512))[t] = o;
    if (out16) {
        __half2* h = (__half2*)(out16 + row * 512);
        h[2 * t]     = __floats2half2_rn(o.x, o.y);
        h[2 * t + 1] = __floats2half2_rn(o.z, o.w);
    }
}

// ---------------- launch ----------------
extern "C" void kernel_launch(void* const* d_in, const int* in_sizes, int n_in,
                              void* d_out, int out_size) {
    const float* x      = (const float*)d_in[0];
    const float* qw     = (const float*)d_in[1];
    const float* kw     = (const float*)d_in[2];
    const float* vw     = (const float*)d_in[3];
    const float* lw     = (const float*)d_in[4];
    const float* gamma1 = (const float*)d_in[5];
    const float* beta1  = (const float*)d_in[6];
    const float* w1     = (const float*)d_in[7];
    const float* b1     = (const float*)d_in[8];
    const float* w2     = (const float*)d_in[9];
    const float* b2     = (const float*)d_in[10];
    const float* gamma2 = (const float*)d_in[11];
    const float* beta2  = (const float*)d_in[12];
    float* out = (float*)d_out;

    __half *x16, *vw16, *WqkT, *lwT, *WfT, *w1T, *w2T, *QK, *VL, *VLt,
           *S16, *H16, *F1;
    float *Mha, *H, *F2;
    cudaGetSymbolAddress((void**)&x16,  g_x16);
    cudaGetSymbolAddress((void**)&vw16, g_vw16);
    cudaGetSymbolAddress((void**)&WqkT, g_WqkT);
    cudaGetSymbolAddress((void**)&lwT,  g_lwT);
    cudaGetSymbolAddress((void**)&WfT,  g_WfT);
    cudaGetSymbolAddress((void**)&w1T,  g_w1T);
    cudaGetSymbolAddress((void**)&w2T,  g_w2T);
    cudaGetSymbolAddress((void**)&QK,   g_QK);
    cudaGetSymbolAddress((void**)&VL,   g_VL);
    cudaGetSymbolAddress((void**)&VLt,  g_VLt);
    cudaGetSymbolAddress((void**)&S16,  g_S16);
    cudaGetSymbolAddress((void**)&Mha,  g_Mha);
    cudaGetSymbolAddress((void**)&H,    g_H);
    cudaGetSymbolAddress((void**)&H16,  g_H16);
    cudaGetSymbolAddress((void**)&F1,   g_F1);
    cudaGetSymbolAddress((void**)&F2,   g_F2);

    cudaFuncSetAttribute(gemm16, cudaFuncAttributeMaxDynamicSharedMemorySize, SMEMSZ);

    dim3 blk(256);
    dim3 tblk(32, 8);
    const float scl = 1.0f / sqrtf(512.0f);

    // ---- prep ordered so ncu (-s 5 -c 1) captures launch #6 = QK gemm ----
    cvt16<<<(TOK*512 + 255)/256, 256>>>(x, x16, TOK*512);                          // 1
    cvt16<<<(8*512*512 + 255)/256, 256>>>(vw, vw16, 8*512*512);                    // 2
    transpose_cvt<<<dim3(2, 16, 8), tblk>>>(qw, WqkT, 512, 64, 512*64, 64*512, scl);      // 3 (scale folded)
    transpose_cvt<<<dim3(2, 16, 8), tblk>>>(kw, WqkT + 512*512, 512, 64, 512*64, 64*512, 1.f); // 4
    transpose_cvt<<<dim3(16, 128, 1), tblk>>>(lw, lwT, 4096, 512, 0, 0, 1.f);      // 5
    gemm16<<<dim3(8, 64, 1), blk, SMEMSZ>>>(x16, WqkT, nullptr, QK, 512,           // 6 <- profiled
        512, 512, 1024, 0,0,0,0,0,0, 1, nullptr, 0);

    transpose_cvt<<<dim3(64, 16, 1), tblk>>>(w1, w1T, 512, 2048, 0, 0, 1.f);
    transpose_cvt<<<dim3(16, 64, 1), tblk>>>(w2, w2T, 2048, 512, 0, 0, 1.f);

    // ---- fused weight: WfT[(h*512+f)][d] = sum_e lw[h*512+e][f] * vw[h][d][e]
    gemm16<<<dim3(4, 4, 8), blk, SMEMSZ>>>(lwT, vw16, nullptr, WfT, 512,
        4096, 512, 512,
        0, 512, 0, 512LL*512, 0, 512LL*512, 8, nullptr, 0);

    // ---- VL = x @ Wfused ----
    gemm16<<<dim3(32, 64, 1), blk, SMEMSZ>>>(x16, WfT, nullptr, VL, 512,
        512, 512, 4096, 0,0,0,0,0,0, 1, nullptr, 0);
    transpose_vl<<<dim3(16, 32, 64), tblk>>>(VL, VLt);

    // ---- scores: S16[b*1024+t][h*1024+t'] = Qs_bh K_bh^T  (scale pre-folded) --
    gemm16<<<dim3(8, 8, 64), blk, SMEMSZ>>>(QK, QK + 512, nullptr, S16, 64,
        1024, 1024, 8192,
        1024LL*1024, 64, 1024LL*1024, 64,
        1024LL*8192, 1024, 8, nullptr, 0);

    softmax_h<<<65536, 256>>>(S16);

    // ---- mha[b] = S16[b] @ VLt[b]^T : M=1024, N=512, K=8192 ----
    gemm16<<<dim3(4, 8, 8), blk, SMEMSZ>>>(S16, VLt, Mha, nullptr, 8192,
        8192, 8192, 512,
        1024LL*8192, 0, 512LL*8192, 0,
        1024LL*512, 0, 1, nullptr, 0);

    add_ln<<<8192, 128>>>(x, Mha, gamma1, beta1, H, H16);

    // ---- FFN ----
    gemm16<<<dim3(16, 64, 1), blk, SMEMSZ>>>(H16, w1T, nullptr, F1, 512,
        512, 512, 2048, 0,0,0,0,0,0, 1, b1, 1);
    gemm16<<<dim3(4, 64, 1), blk, SMEMSZ>>>(F1, w2T, F2, nullptr, 2048,
        2048, 2048, 512, 0,0,0,0,0,0, 1, b2, 0);

    add_ln<<<8192, 128>>>(H, F2, gamma2, beta2, out, nullptr);
}

// round 17
// speedup vs baseline: 1.0520x; 1.0520x over previous
#include <cuda_runtime.h>
#include <cuda_fp16.h>
#include <math.h>
#include <stdint.h>

// ---------------- problem constants ----------------
#define D_MODEL 512
#define SEQ     1024
#define BATCH   8
#define NHEADS  8
#define UDIM    64
#define FF      2048
#define TOK     (BATCH*SEQ)          // 8192
#define LN_EPS  1e-3f

// ---------------- scratch (static device, allocation-guard safe) -------------
__device__ __half g_x16[TOK*D_MODEL];
__device__ __half g_vw16[NHEADS*D_MODEL*D_MODEL];    // vw cvt, [h][d][e]
__device__ __half g_WqkT[2*D_MODEL*D_MODEL];         // rows 0-511: WqT, 512-1023: WkT
__device__ __half g_lwT[D_MODEL*NHEADS*D_MODEL];     // [f][h*512+e]
__device__ __half g_WfT[NHEADS*D_MODEL*D_MODEL];     // [(h*512+f)][d]  (fused vw@lw)
__device__ __half g_w1T[FF*D_MODEL];                 // [2048][512]
__device__ __half g_w2T[D_MODEL*FF];                 // [512][2048]
__device__ __half g_QK [TOK*2*D_MODEL];              // [t][q:0-511 | k:512-1023]
__device__ __half g_VL [TOK*NHEADS*D_MODEL];         // [t][(h*512+f)]
__device__ __half g_VLt[(size_t)BATCH*D_MODEL*NHEADS*SEQ];  // [(b*512+f)][h*1024+t']
__device__ __half g_S16[(size_t)TOK*NHEADS*SEQ];     // [b*1024+t][h*1024+t'] fp16
__device__ float  g_Mha[TOK*D_MODEL];
__device__ float  g_H  [TOK*D_MODEL];
__device__ __half g_H16[TOK*D_MODEL];
__device__ __half g_F1 [TOK*FF];
__device__ float  g_F2 [TOK*D_MODEL];

// ---------------- cp.async helpers ----------------
__device__ __forceinline__ void cp_async16(unsigned int dst, const void* src) {
    asm volatile("cp.async.cg.shared.global [%0], [%1], 16;\n" :: "r"(dst), "l"(src));
}
__device__ __forceinline__ void cp_commit() {
    asm volatile("cp.async.commit_group;\n");
}
template<int N>
__device__ __forceinline__ void cp_wait() {
    asm volatile("cp.async.wait_group %0;\n" :: "n"(N));
}

// ---------------- elementwise fp32 -> fp16 ----------------
__global__ void cvt16(const float* __restrict__ in, __half* __restrict__ out, int n) {
    int i = blockIdx.x * blockDim.x + threadIdx.x;
    if (i < n) out[i] = __float2half(in[i]);
}

// ---------------- tiled transpose + cvt: in[z][R][C] fp32 -> out[z][C][R] fp16 --
__global__ void transpose_cvt(const float* __restrict__ in, __half* __restrict__ out,
                              int R, int C, long long inZ, long long outZ) {
    in  += (long long)blockIdx.z * inZ;
    out += (long long)blockIdx.z * outZ;
    __shared__ float s[32][33];
    int c0 = blockIdx.x * 32, r0 = blockIdx.y * 32;
    int tx = threadIdx.x, ty = threadIdx.y;
#pragma unroll
    for (int j = 0; j < 4; j++)
        s[ty + 8 * j][tx] = in[(long long)(r0 + ty + 8 * j) * C + c0 + tx];
    __syncthreads();
#pragma unroll
    for (int j = 0; j < 4; j++)
        out[(long long)(c0 + ty + 8 * j) * R + r0 + tx] = __float2half(s[tx][ty + 8 * j]);
}

// ---------------- VL transpose: VL[t][(h*512+f)] -> VLt[(b*512+f)][h*1024+t'] --
__global__ void transpose_vl(const __half* __restrict__ VL, __half* __restrict__ VLt) {
    int z = blockIdx.z, b = z >> 3, h = z & 7;
    int c0 = blockIdx.x * 32;   // f
    int r0 = blockIdx.y * 32;   // t'
    __shared__ __half s[32][40];
    int tx = threadIdx.x, ty = threadIdx.y;
#pragma unroll
    for (int j = 0; j < 4; j++)
        s[ty + 8 * j][tx] = VL[(size_t)(b * 1024 + r0 + ty + 8 * j) * 4096 + h * 512 + c0 + tx];
    __syncthreads();
#pragma unroll
    for (int j = 0; j < 4; j++)
        VLt[(size_t)(b * 512 + c0 + ty + 8 * j) * 8192 + h * 1024 + r0 + tx] = s[tx][ty + 8 * j];
}

// ---------------- fp16 NT tensor-core GEMM  128x128xK, 256 thr (R15 proven) ----
// 8 warps (2x4), 64x32 warp tile.  mma.sync.m16n8k16 fp32-accum.
// smem rows 32 halves (64B), 16B-group swizzle j -> j ^ ((row>>1)&3).
// k-remap: thread t4 carries global k {4t4..4t4+3}; same bijection A and B.
// 4-stage cp.async pipeline in 64KB dynamic smem; ONE barrier per iteration.
// K%32==0, M,N%128==0.
#define STAGES 4
#define STG_BYTES 16384u            // per stage: A 8KB + B 8KB
#define SMEMSZ (STAGES * 16384)

__global__ void __launch_bounds__(256, 2) gemm16(
    const __half* __restrict__ A, const __half* __restrict__ B,
    float* __restrict__ C32, __half* __restrict__ C16,
    int K, int lda, int ldb, int ldc,
    long long aOut, long long aIn, long long bOut, long long bIn,
    long long cOut, long long cIn, int HB,
    const float* __restrict__ bias, int relu)
{
    extern __shared__ char smem_raw[];
    int z  = blockIdx.z;
    int zo = z / HB, zi = z % HB;
    A += zo * aOut + (long long)zi * aIn;
    B += zo * bOut + (long long)zi * bIn;
    long long coff = zo * cOut + (long long)zi * cIn;

    const int tid  = threadIdx.x;
    const int lane = tid & 31;
    const int wid  = tid >> 5;
    const int wm   = wid >> 2;
    const int wn   = wid & 3;
    const int g    = lane >> 2;
    const int t4   = lane & 3;

    const int bm = blockIdx.y * 128;
    const int bn = blockIdx.x * 128;
    const int KT = K >> 5;

    const bool isA = (tid < 128);
    const int  lrow = tid & 127;
    const int  lsw  = (lrow >> 1) & 3;
    const __half* Lg = isA ? (A + (long long)(bm + lrow) * lda)
                           : (B + (long long)(bn + lrow) * ldb);

    unsigned int sb;
    asm("{ .reg .u64 t; cvta.to.shared.u64 t, %1; cvt.u32.u64 %0, t; }"
        : "=r"(sb) : "l"(smem_raw));
    unsigned int sBase = sb + (isA ? 0u : 8192u);

    auto issue = [&](int kt, int s) {
        unsigned int st = sBase + (unsigned int)s * STG_BYTES;
        const __half* src = Lg + (long long)kt * 32;
#pragma unroll
        for (int j = 0; j < 4; j++)
            cp_async16(st + (unsigned int)(lrow * 4 + (j ^ lsw)) * 16, src + j * 8);
    };

    float acc[4][4][4];
#pragma unroll
    for (int mi = 0; mi < 4; mi++)
#pragma unroll
        for (int ni = 0; ni < 4; ni++)
#pragma unroll
            for (int r = 0; r < 4; r++) acc[mi][ni][r] = 0.f;

#pragma unroll
    for (int s = 0; s < STAGES - 1; s++) {
        if (s < KT) issue(s, s);
        cp_commit();
    }

    for (int kt = 0; kt < KT; kt++) {
        cp_wait<STAGES - 2>();
        __syncthreads();
        if (kt + STAGES - 1 < KT) issue(kt + STAGES - 1, (kt + STAGES - 1) % STAGES);
        cp_commit();

        const int st = kt % STAGES;
        const uint2* As2 = (const uint2*)(smem_raw + st * STG_BYTES);
        const uint2* Bs2 = (const uint2*)(smem_raw + st * STG_BYTES + 8192);
#pragma unroll
        for (int kk = 0; kk < 2; kk++) {
            const int jb = kk * 2 + (t4 >> 1);
            uint2 afr[4][2];
#pragma unroll
            for (int mi = 0; mi < 4; mi++) {
                const int r0 = wm * 64 + mi * 16 + g;
                const int r1 = r0 + 8;
                afr[mi][0] = As2[r0 * 8 + ((jb ^ ((r0 >> 1) & 3)) << 1) + (t4 & 1)];
                afr[mi][1] = As2[r1 * 8 + ((jb ^ ((r1 >> 1) & 3)) << 1) + (t4 & 1)];
            }
#pragma unroll
            for (int ni = 0; ni < 4; ni++) {
                const int n0 = wn * 32 + ni * 8 + g;
                const uint2 bfr = Bs2[n0 * 8 + ((jb ^ ((n0 >> 1) & 3)) << 1) + (t4 & 1)];
#pragma unroll
                for (int mi = 0; mi < 4; mi++) {
                    asm volatile(
                        "mma.sync.aligned.m16n8k16.row.col.f32.f16.f16.f32 "
                        "{%0,%1,%2,%3},{%4,%5,%6,%7},{%8,%9},{%0,%1,%2,%3};\n"
                        : "+f"(acc[mi][ni][0]), "+f"(acc[mi][ni][1]),
                          "+f"(acc[mi][ni][2]), "+f"(acc[mi][ni][3])
                        : "r"(afr[mi][0].x), "r"(afr[mi][1].x),
                          "r"(afr[mi][0].y), "r"(afr[mi][1].y),
                          "r"(bfr.x), "r"(bfr.y));
                }
            }
        }
        // no bottom barrier: next iteration's top barrier provides ordering
    }

    // ---- epilogue ----
#pragma unroll
    for (int mi = 0; mi < 4; mi++) {
        const int row0 = bm + wm * 64 + mi * 16 + g;
#pragma unroll
        for (int ni = 0; ni < 4; ni++) {
            const int col = bn + wn * 32 + ni * 8 + t4 * 2;
            float v0 = acc[mi][ni][0], v1 = acc[mi][ni][1];
            float v2 = acc[mi][ni][2], v3 = acc[mi][ni][3];
            if (bias) {
                float b0 = bias[col], b1 = bias[col + 1];
                v0 += b0; v1 += b1; v2 += b0; v3 += b1;
            }
            if (relu) {
                v0 = fmaxf(v0, 0.f); v1 = fmaxf(v1, 0.f);
                v2 = fmaxf(v2, 0.f); v3 = fmaxf(v3, 0.f);
            }
            long long o0 = coff + (long long)row0 * ldc + col;
            long long o1 = coff + (long long)(row0 + 8) * ldc + col;
            if (C32) {
                *(float2*)(C32 + o0) = make_float2(v0, v1);
                *(float2*)(C32 + o1) = make_float2(v2, v3);
            }
            if (C16) {
                *(__half2*)(C16 + o0) = __floats2half2_rn(v0, v1);
                *(__half2*)(C16 + o1) = __floats2half2_rn(v2, v3);
            }
        }
    }
}

// ---------------- in-place fp16 softmax over 1024 cols (fp32 math) -----------
__global__ void softmax_h(__half* __restrict__ P, float scale) {
    long long row = blockIdx.x;
    __half2* p = (__half2*)(P + row * 1024);
    int t = threadIdx.x;
    __half2 h0 = p[2 * t], h1 = p[2 * t + 1];
    float2 f0 = __half22float2(h0), f1 = __half22float2(h1);
    float v0 = f0.x * scale, v1 = f0.y * scale;
    float v2 = f1.x * scale, v3 = f1.y * scale;

    __shared__ float red[256];
    float m = fmaxf(fmaxf(v0, v1), fmaxf(v2, v3));
    red[t] = m;
    __syncthreads();
#pragma unroll
    for (int s = 128; s > 0; s >>= 1) {
        if (t < s) red[t] = fmaxf(red[t], red[t + s]);
        __syncthreads();
    }
    m = red[0];
    __syncthreads();

    v0 = __expf(v0 - m); v1 = __expf(v1 - m);
    v2 = __expf(v2 - m); v3 = __expf(v3 - m);
    red[t] = v0 + v1 + v2 + v3;
    __syncthreads();
#pragma unroll
    for (int s = 128; s > 0; s >>= 1) {
        if (t < s) red[t] += red[t + s];
        __syncthreads();
    }
    float inv = 1.f / red[0];
    p[2 * t]     = __floats2half2_rn(v0 * inv, v1 * inv);
    p[2 * t + 1] = __floats2half2_rn(v2 * inv, v3 * inv);
}

// ---------------- out = LayerNorm(a + b); optional fp16 copy ----------------
__global__ void add_ln(const float* __restrict__ a, const float* __restrict__ b,
                       const float* __restrict__ gamma, const float* __restrict__ beta,
                       float* __restrict__ out, __half* __restrict__ out16) {
    long long row = blockIdx.x;
    int t = threadIdx.x;
    const float4 va = ((const float4*)(a + row * 512))[t];
    const float4 vb = ((const float4*)(b + row * 512))[t];
    float x0 = va.x + vb.x, x1 = va.y + vb.y, x2 = va.z + vb.z, x3 = va.w + vb.w;

    __shared__ float red[128];
    red[t] = x0 + x1 + x2 + x3;
    __syncthreads();
#pragma unroll
    for (int s = 64; s > 0; s >>= 1) {
        if (t < s) red[t] += red[t + s];
        __syncthreads();
    }
    float mean = red[0] * (1.f / 512.f);
    __syncthreads();

    float d0 = x0 - mean, d1 = x1 - mean, d2 = x2 - mean, d3 = x3 - mean;
    red[t] = d0 * d0 + d1 * d1 + d2 * d2 + d3 * d3;
    __syncthreads();
#pragma unroll
    for (int s = 64; s > 0; s >>= 1) {
        if (t < s) red[t] += red[t + s];
        __syncthreads();
    }
    float var = red[0] * (1.f / 512.f);
    float inv = rsqrtf(var + LN_EPS);

    const float4 gm = ((const float4*)gamma)[t];
    const float4 be = ((const float4*)beta)[t];
    float4 o;
    o.x = gm.x * (d0 * inv) + be.x;
    o.y = gm.y * (d1 * inv) + be.y;
    o.z = gm.z * (d2 * inv) + be.z;
    o.w = gm.w * (d3 * inv) + be.w;
    ((float4*)(out + row * 512))[t] = o;
    if (out16) {
        __half2* h = (__half2*)(out16 + row * 512);
        h[2 * t]     = __floats2half2_rn(o.x, o.y);
        h[2 * t + 1] = __floats2half2_rn(o.z, o.w);
    }
}

// ---------------- launch ----------------
extern "C" void kernel_launch(void* const* d_in, const int* in_sizes, int n_in,
                              void* d_out, int out_size) {
    const float* x      = (const float*)d_in[0];
    const float* qw     = (const float*)d_in[1];
    const float* kw     = (const float*)d_in[2];
    const float* vw     = (const float*)d_in[3];
    const float* lw     = (const float*)d_in[4];
    const float* gamma1 = (const float*)d_in[5];
    const float* beta1  = (const float*)d_in[6];
    const float* w1     = (const float*)d_in[7];
    const float* b1     = (const float*)d_in[8];
    const float* w2     = (const float*)d_in[9];
    const float* b2     = (const float*)d_in[10];
    const float* gamma2 = (const float*)d_in[11];
    const float* beta2  = (const float*)d_in[12];
    float* out = (float*)d_out;

    __half *x16, *vw16, *WqkT, *lwT, *WfT, *w1T, *w2T, *QK, *VL, *VLt,
           *S16, *H16, *F1;
    float *Mha, *H, *F2;
    cudaGetSymbolAddress((void**)&x16,  g_x16);
    cudaGetSymbolAddress((void**)&vw16, g_vw16);
    cudaGetSymbolAddress((void**)&WqkT, g_WqkT);
    cudaGetSymbolAddress((void**)&lwT,  g_lwT);
    cudaGetSymbolAddress((void**)&WfT,  g_WfT);
    cudaGetSymbolAddress((void**)&w1T,  g_w1T);
    cudaGetSymbolAddress((void**)&w2T,  g_w2T);
    cudaGetSymbolAddress((void**)&QK,   g_QK);
    cudaGetSymbolAddress((void**)&VL,   g_VL);
    cudaGetSymbolAddress((void**)&VLt,  g_VLt);
    cudaGetSymbolAddress((void**)&S16,  g_S16);
    cudaGetSymbolAddress((void**)&Mha,  g_Mha);
    cudaGetSymbolAddress((void**)&H,    g_H);
    cudaGetSymbolAddress((void**)&H16,  g_H16);
    cudaGetSymbolAddress((void**)&F1,   g_F1);
    cudaGetSymbolAddress((void**)&F2,   g_F2);

    cudaFuncSetAttribute(gemm16, cudaFuncAttributeMaxDynamicSharedMemorySize, SMEMSZ);

    dim3 blk(256);
    dim3 tblk(32, 8);

    // ---- side stream for the V/FFN-weight chain (capture fork via events) ----
    cudaStream_t s1;
    cudaStreamCreateWithFlags(&s1, cudaStreamNonBlocking);
    cudaEvent_t evX, evJ;
    cudaEventCreateWithFlags(&evX, cudaEventDisableTiming);
    cudaEventCreateWithFlags(&evJ, cudaEventDisableTiming);

    // x16 is needed by both chains: produce it first on the main (legacy) stream
    cvt16<<<(TOK*512 + 255)/256, 256>>>(x, x16, TOK*512);
    cudaEventRecord(evX, 0);

    // ---- Chain B on s1: vw/lw/w1/w2 prep -> Wf fuse -> VL -> VLt ----
    cudaStreamWaitEvent(s1, evX, 0);
    cvt16<<<(8*512*512 + 255)/256, 256, 0, s1>>>(vw, vw16, 8*512*512);
    transpose_cvt<<<dim3(16, 128, 1), tblk, 0, s1>>>(lw, lwT, 4096, 512, 0, 0);
    transpose_cvt<<<dim3(64, 16, 1), tblk, 0, s1>>>(w1, w1T, 512, 2048, 0, 0);
    transpose_cvt<<<dim3(16, 64, 1), tblk, 0, s1>>>(w2, w2T, 2048, 512, 0, 0);
    gemm16<<<dim3(4, 4, 8), blk, SMEMSZ, s1>>>(lwT, vw16, nullptr, WfT, 512,
        4096, 512, 512,
        0, 512, 0, 512LL*512, 0, 512LL*512, 8, nullptr, 0);
    gemm16<<<dim3(32, 64, 1), blk, SMEMSZ, s1>>>(x16, WfT, nullptr, VL, 512,
        512, 512, 4096, 0,0,0,0,0,0, 1, nullptr, 0);
    transpose_vl<<<dim3(16, 32, 64), tblk, 0, s1>>>(VL, VLt);
    cudaEventRecord(evJ, s1);

    // ---- Chain A on legacy stream: QK -> scores -> softmax ----
    transpose_cvt<<<dim3(2, 16, 8), tblk>>>(qw, WqkT, 512, 64, 512*64, 64*512);
    transpose_cvt<<<dim3(2, 16, 8), tblk>>>(kw, WqkT + 512*512, 512, 64, 512*64, 64*512);
    gemm16<<<dim3(8, 64, 1), blk, SMEMSZ>>>(x16, WqkT, nullptr, QK, 512,
        512, 512, 1024, 0,0,0,0,0,0, 1, nullptr, 0);
    gemm16<<<dim3(8, 8, 64), blk, SMEMSZ>>>(QK, QK + 512, nullptr, S16, 64,
        1024, 1024, 8192,
        1024LL*1024, 64, 1024LL*1024, 64,
        1024LL*8192, 1024, 8, nullptr, 0);
    softmax_h<<<65536, 256>>>(S16, 1.0f / sqrtf(512.0f));

    // ---- join: mha needs S16 (chain A) and VLt (chain B) ----
    cudaStreamWaitEvent(0, evJ, 0);
    gemm16<<<dim3(4, 8, 8), blk, SMEMSZ>>>(S16, VLt, Mha, nullptr, 8192,
        8192, 8192, 512,
        1024LL*8192, 0, 512LL*8192, 0,
        1024LL*512, 0, 1, nullptr, 0);

    add_ln<<<8192, 128>>>(x, Mha, gamma1, beta1, H, H16);

    // ---- FFN ----
    gemm16<<<dim3(16, 64, 1), blk, SMEMSZ>>>(H16, w1T, nullptr, F1, 512,
        512, 512, 2048, 0,0,0,0,0,0, 1, b1, 1);
    gemm16<<<dim3(4, 64, 1), blk, SMEMSZ>>>(F1, w2T, F2, nullptr, 2048,
        2048, 2048, 512, 0,0,0,0,0,0, 1, b2, 0);

    add_ln<<<8192, 128>>>(H, F2, gamma2, beta2, out, nullptr);
}